// round 5
// baseline (speedup 1.0000x reference)
#include <cuda_runtime.h>
#include <cstdint>

#define NN 100000
#define EE 1600000
#define IND 128
#define HD  64
#define EPSV 1e-5f

// ---------------- scratch (device globals: allocation-free) ----------------
__device__ __align__(16) float  g_h0 [(size_t)NN * HD];
__device__ __align__(16) float  g_g  [(size_t)NN * HD];
__device__ __align__(16) float  g_acc[(size_t)NN * HD];
__device__ __align__(16) float  g_pre[(size_t)NN * HD];
__device__ float  g_dinv[NN];
__device__ int    g_deg [NN];
__device__ double g_sum [IND];
__device__ double g_sqs [IND];

__device__ __forceinline__ float* bufptr(int s) {
    switch (s) {
        case 0: return g_h0;
        case 1: return g_g;
        case 2: return g_acc;
        default: return g_pre;
    }
}

// ---------------- zero / init kernels ----------------
__global__ void zero_init_k() {   // deg + stats(128)
    int i = blockIdx.x * blockDim.x + threadIdx.x;
    if (i < NN) g_deg[i] = 0;
    if (i < IND) { g_sum[i] = 0.0; g_sqs[i] = 0.0; }
}

__global__ void zero_acc_k() {    // acc (N*64 floats) + stats(64)
    int i = blockIdx.x * blockDim.x + threadIdx.x;
    if (i < NN * (HD / 4)) reinterpret_cast<float4*>(g_acc)[i] = make_float4(0.f, 0.f, 0.f, 0.f);
    if (i < HD) { g_sum[i] = 0.0; g_sqs[i] = 0.0; }
}

// ---------------- degree ----------------
__global__ void deg_k(const int* __restrict__ ei) {
    int e = blockIdx.x * blockDim.x + threadIdx.x;
    if (e < EE) atomicAdd(&g_deg[ei[EE + e]], 1);
}

__global__ void dinv_k() {
    int i = blockIdx.x * blockDim.x + threadIdx.x;
    if (i < NN) g_dinv[i] = rsqrtf((float)(g_deg[i] + 1));   // +1 = self loop
}

// ---------------- BN stats over x [N,128] ----------------
__global__ void __launch_bounds__(256) statsx_k(const float* __restrict__ X) {
    int c   = threadIdx.x & 127;
    int rep = threadIdx.x >> 7;      // 0..1
    double s = 0.0, q = 0.0;
    for (int r = blockIdx.x * 2 + rep; r < NN; r += gridDim.x * 2) {
        float v = X[(long)r * IND + c];
        s += (double)v;
        q += (double)v * (double)v;
    }
    __shared__ double ss[256], qq[256];
    ss[threadIdx.x] = s; qq[threadIdx.x] = q;
    __syncthreads();
    if (threadIdx.x < 128) {
        s = ss[c] + ss[c + 128];
        q = qq[c] + qq[c + 128];
        atomicAdd(&g_sum[c], s);
        atomicAdd(&g_sqs[c], q);
    }
}

// ---------------- fused GEMM: [N,IN] @ [IN,64] ----------------
template<int IN, bool BNIN, bool RELUIN, bool RELUOUT, bool SCALED>
__global__ void __launch_bounds__(128) gemm_k(
    const float* __restrict__ Xext, int xsel,
    const float* __restrict__ W,
    const float* __restrict__ bias,
    const float* __restrict__ bng,
    const float* __restrict__ bnb,
    int osel)
{
    __shared__ float Ws[32 * 64];
    __shared__ float xs[128 * 33];
    __shared__ float sc[IND], sh[IND];

    const float* X  = (xsel < 0) ? Xext : bufptr(xsel);
    float*      out = bufptr(osel);

    int tid = threadIdx.x;
    if (BNIN) {
        if (tid < IN) {
            double m = g_sum[tid] / (double)NN;
            double v = g_sqs[tid] / (double)NN - m * m;
            float  s = bng[tid] * rsqrtf((float)v + EPSV);
            sc[tid] = s;
            sh[tid] = bnb[tid] - (float)m * s;
        }
        __syncthreads();
    }

    int row = blockIdx.x * 128 + tid;
    float acc[64];
#pragma unroll
    for (int j = 0; j < 64; j++) acc[j] = 0.f;

    for (int k0 = 0; k0 < IN; k0 += 32) {
#pragma unroll
        for (int i = 0; i < 16; i++) {
            int idx = i * 128 + tid;                 // 2048 elems
            Ws[idx] = W[(k0 + (idx >> 6)) * 64 + (idx & 63)];
        }
        int kk = tid & 31, rbase = tid >> 5;
#pragma unroll
        for (int i = 0; i < 32; i++) {
            int r  = i * 4 + rbase;
            int gr = blockIdx.x * 128 + r;
            float v = (gr < NN) ? X[(long)gr * IN + k0 + kk] : 0.f;
            if (BNIN) {
                v = v * sc[k0 + kk] + sh[k0 + kk];
                if (RELUIN) v = fmaxf(v, 0.f);
            }
            xs[r * 33 + kk] = v;
        }
        __syncthreads();
#pragma unroll
        for (int q = 0; q < 32; q++) {
            float xv = xs[tid * 33 + q];
#pragma unroll
            for (int j = 0; j < 16; j++) {
                float4 w = *(const float4*)&Ws[q * 64 + j * 4];
                acc[j * 4 + 0] = fmaf(xv, w.x, acc[j * 4 + 0]);
                acc[j * 4 + 1] = fmaf(xv, w.y, acc[j * 4 + 1]);
                acc[j * 4 + 2] = fmaf(xv, w.z, acc[j * 4 + 2]);
                acc[j * 4 + 3] = fmaf(xv, w.w, acc[j * 4 + 3]);
            }
        }
        __syncthreads();
    }

    if (row < NN) {
        float d = 1.f;
        if (SCALED) d = g_dinv[row];
#pragma unroll
        for (int j = 0; j < 16; j++) {
            float4 o;
            o.x = acc[j * 4 + 0]; o.y = acc[j * 4 + 1];
            o.z = acc[j * 4 + 2]; o.w = acc[j * 4 + 3];
            if (RELUOUT) {
                o.x = fmaxf(o.x + bias[j * 4 + 0], 0.f);
                o.y = fmaxf(o.y + bias[j * 4 + 1], 0.f);
                o.z = fmaxf(o.z + bias[j * 4 + 2], 0.f);
                o.w = fmaxf(o.w + bias[j * 4 + 3], 0.f);
            } else if (SCALED) {
                o.x *= d; o.y *= d; o.z *= d; o.w *= d;
            }
            *(float4*)&out[(long)row * 64 + j * 4] = o;
        }
    }
}

// ---------------- edge scatter: acc[dst] += g[src], scalar atomics ----------------
// 16 lanes per edge; each lane: 1x LDG.128 gather + 4x scalar REDG.32
__global__ void __launch_bounds__(256) scatter_k(const int* __restrict__ ei) {
    long long idx = (long long)blockIdx.x * blockDim.x + threadIdx.x;
    int e = (int)(idx >> 4);
    int l = (int)(idx & 15);
    if (e >= EE) return;
    int s = ei[e];
    int d = ei[EE + e];
    float4 v = __ldg(reinterpret_cast<const float4*>(g_g) + ((long)s * 16 + l));
    float* p = &g_acc[(long)d * 64 + l * 4];
    atomicAdd(p + 0, v.x);
    atomicAdd(p + 1, v.y);
    atomicAdd(p + 2, v.z);
    atomicAdd(p + 3, v.w);
}

// ---------------- finalize conv (+bias) and accumulate next-BN stats ----------------
__global__ void __launch_bounds__(256) finstats_k(const float* __restrict__ bias) {
    int c   = threadIdx.x & 63;
    int rep = threadIdx.x >> 6;   // 0..3
    double s = 0.0, q = 0.0;
    for (int r = blockIdx.x * 4 + rep; r < NN; r += gridDim.x * 4) {
        float d = g_dinv[r];
        int idx = r * 64 + c;
        float v = d * (g_acc[idx] + g_g[idx]) + bias[c];
        g_pre[idx] = v;
        s += (double)v;
        q += (double)v * (double)v;
    }
    __shared__ double ss[256], qq[256];
    ss[threadIdx.x] = s; qq[threadIdx.x] = q;
    __syncthreads();
    if (threadIdx.x < 64) {
        s = ss[c] + ss[c + 64] + ss[c + 128] + ss[c + 192];
        q = qq[c] + qq[c + 64] + qq[c + 128] + qq[c + 192];
        atomicAdd(&g_sum[c], s);
        atomicAdd(&g_sqs[c], q);
    }
}

// ---------------- final BN apply ----------------
__global__ void __launch_bounds__(256) bnapply_k(const float* __restrict__ gam,
                                                 const float* __restrict__ bet,
                                                 float* __restrict__ out) {
    int idx = blockIdx.x * blockDim.x + threadIdx.x;
    if (idx >= NN * HD) return;
    int c = idx & 63;
    double m = g_sum[c] / (double)NN;
    double v = g_sqs[c] / (double)NN - m * m;
    float scl = gam[c] * rsqrtf((float)v + EPSV);
    out[idx] = (g_pre[idx] - (float)m) * scl + bet[c];
}

// ---------------- launch ----------------
extern "C" void kernel_launch(void* const* d_in, const int* in_sizes, int n_in,
                              void* d_out, int out_size) {
    const float* x       = (const float*)d_in[0];
    const int*   ei      = (const int*)d_in[1];     // int32: JAX w/o x64 emits int32
    const float* bn_in_g = (const float*)d_in[2];
    const float* bn_in_b = (const float*)d_in[3];
    const float* Wp      = (const float*)d_in[4];
    const float* bp      = (const float*)d_in[5];
    const float* W1      = (const float*)d_in[6];
    const float* b1      = (const float*)d_in[7];
    const float* bn1_g   = (const float*)d_in[8];
    const float* bn1_b   = (const float*)d_in[9];
    const float* W2      = (const float*)d_in[10];
    const float* b2      = (const float*)d_in[11];
    const float* bn2_g   = (const float*)d_in[12];
    const float* bn2_b   = (const float*)d_in[13];
    float* out = (float*)d_out;

    const int GB_N    = (NN + 255) / 256;            // 391
    const int GB_E    = (EE + 255) / 256;            // 6250
    const int GB_GEMM = (NN + 127) / 128;            // 782
    const int GB_ACC  = (NN * 16 + 255) / 256;       // 6250
    const int GB_SCAT = (int)(((long long)EE * 16 + 255) / 256);  // 100000
    const int GB_OUT  = (NN * HD + 255) / 256;       // 25000

    // degree + input BN stats
    zero_init_k<<<GB_N, 256>>>();
    deg_k<<<GB_E, 256>>>(ei);
    statsx_k<<<256, 256>>>(x);
    dinv_k<<<GB_N, 256>>>();

    // h0 = relu(BN(x) @ Wp + bp)
    gemm_k<IND, true, false, true, false><<<GB_GEMM, 128>>>(x, -1, Wp, bp, bn_in_g, bn_in_b, 0);

    // conv1: g = dinv * (h0 @ W1); acc = scatter; pre = dinv*(acc+g)+b1 (+bn1 stats)
    gemm_k<HD, false, false, false, true><<<GB_GEMM, 128>>>(nullptr, 0, W1, nullptr, nullptr, nullptr, 1);
    zero_acc_k<<<GB_ACC, 256>>>();
    scatter_k<<<GB_SCAT, 256>>>(ei);
    finstats_k<<<256, 256>>>(b1);

    // conv2: g = dinv * (relu(BN1(pre)) @ W2); scatter; pre = dinv*(acc+g)+b2 (+bn2 stats)
    gemm_k<HD, true, true, false, true><<<GB_GEMM, 128>>>(nullptr, 3, W2, nullptr, bn1_g, bn1_b, 1);
    zero_acc_k<<<GB_ACC, 256>>>();
    scatter_k<<<GB_SCAT, 256>>>(ei);
    finstats_k<<<256, 256>>>(b2);

    // out = BN2(pre)
    bnapply_k<<<GB_OUT, 256>>>(bn2_g, bn2_b, out);
}

// round 6
// speedup vs baseline: 1.3165x; 1.3165x over previous
#include <cuda_runtime.h>
#include <cstdint>

#define NN 100000
#define EE 1600000
#define IND 128
#define HD  64
#define EPSV 1e-5f

// ---------------- scratch (device globals: allocation-free) ----------------
__device__ __align__(16) float  g_h0 [(size_t)NN * HD];
__device__ __align__(16) float  g_g  [(size_t)NN * HD];
__device__ __align__(16) float  g_acc[(size_t)NN * HD];
__device__ __align__(16) float  g_pre[(size_t)NN * HD];
__device__ float  g_dinv[NN];
__device__ int    g_deg [NN];
__device__ double g_sum [IND];
__device__ double g_sqs [IND];

__device__ __forceinline__ float* bufptr(int s) {
    switch (s) {
        case 0: return g_h0;
        case 1: return g_g;
        case 2: return g_acc;
        default: return g_pre;
    }
}

// ---------------- zero / init kernels ----------------
__global__ void zero_init_k() {   // deg + stats(128)
    int i = blockIdx.x * blockDim.x + threadIdx.x;
    if (i < NN) g_deg[i] = 0;
    if (i < IND) { g_sum[i] = 0.0; g_sqs[i] = 0.0; }
}

__global__ void zero_acc_k() {    // acc (N*64 floats) + stats(64)
    int i = blockIdx.x * blockDim.x + threadIdx.x;
    if (i < NN * (HD / 4)) reinterpret_cast<float4*>(g_acc)[i] = make_float4(0.f, 0.f, 0.f, 0.f);
    if (i < HD) { g_sum[i] = 0.0; g_sqs[i] = 0.0; }
}

// ---------------- degree ----------------
__global__ void deg_k(const int* __restrict__ ei) {
    int e = blockIdx.x * blockDim.x + threadIdx.x;
    if (e < EE) atomicAdd(&g_deg[ei[EE + e]], 1);
}

__global__ void dinv_k() {
    int i = blockIdx.x * blockDim.x + threadIdx.x;
    if (i < NN) g_dinv[i] = rsqrtf((float)(g_deg[i] + 1));   // +1 = self loop
}

// ---------------- BN stats over x [N,128] ----------------
__global__ void __launch_bounds__(256) statsx_k(const float* __restrict__ X) {
    int c   = threadIdx.x & 127;
    int rep = threadIdx.x >> 7;      // 0..1
    double s = 0.0, q = 0.0;
    for (int r = blockIdx.x * 2 + rep; r < NN; r += gridDim.x * 2) {
        float v = X[(long)r * IND + c];
        s += (double)v;
        q += (double)v * (double)v;
    }
    __shared__ double ss[256], qq[256];
    ss[threadIdx.x] = s; qq[threadIdx.x] = q;
    __syncthreads();
    if (threadIdx.x < 128) {
        s = ss[c] + ss[c + 128];
        q = qq[c] + qq[c + 128];
        atomicAdd(&g_sum[c], s);
        atomicAdd(&g_sqs[c], q);
    }
}

// ---------------- fused GEMM: [N,IN] @ [IN,64] ----------------
template<int IN, bool BNIN, bool RELUIN, bool RELUOUT, bool SCALED>
__global__ void __launch_bounds__(128) gemm_k(
    const float* __restrict__ Xext, int xsel,
    const float* __restrict__ W,
    const float* __restrict__ bias,
    const float* __restrict__ bng,
    const float* __restrict__ bnb,
    int osel)
{
    __shared__ float Ws[32 * 64];
    __shared__ float xs[128 * 33];
    __shared__ float sc[IND], sh[IND];

    const float* X  = (xsel < 0) ? Xext : bufptr(xsel);
    float*      out = bufptr(osel);

    int tid = threadIdx.x;
    if (BNIN) {
        if (tid < IN) {
            double m = g_sum[tid] / (double)NN;
            double v = g_sqs[tid] / (double)NN - m * m;
            float  s = bng[tid] * rsqrtf((float)v + EPSV);
            sc[tid] = s;
            sh[tid] = bnb[tid] - (float)m * s;
        }
        __syncthreads();
    }

    int row = blockIdx.x * 128 + tid;
    float acc[64];
#pragma unroll
    for (int j = 0; j < 64; j++) acc[j] = 0.f;

    for (int k0 = 0; k0 < IN; k0 += 32) {
#pragma unroll
        for (int i = 0; i < 16; i++) {
            int idx = i * 128 + tid;                 // 2048 elems
            Ws[idx] = W[(k0 + (idx >> 6)) * 64 + (idx & 63)];
        }
        int kk = tid & 31, rbase = tid >> 5;
#pragma unroll
        for (int i = 0; i < 32; i++) {
            int r  = i * 4 + rbase;
            int gr = blockIdx.x * 128 + r;
            float v = (gr < NN) ? X[(long)gr * IN + k0 + kk] : 0.f;
            if (BNIN) {
                v = v * sc[k0 + kk] + sh[k0 + kk];
                if (RELUIN) v = fmaxf(v, 0.f);
            }
            xs[r * 33 + kk] = v;
        }
        __syncthreads();
#pragma unroll
        for (int q = 0; q < 32; q++) {
            float xv = xs[tid * 33 + q];
#pragma unroll
            for (int j = 0; j < 16; j++) {
                float4 w = *(const float4*)&Ws[q * 64 + j * 4];
                acc[j * 4 + 0] = fmaf(xv, w.x, acc[j * 4 + 0]);
                acc[j * 4 + 1] = fmaf(xv, w.y, acc[j * 4 + 1]);
                acc[j * 4 + 2] = fmaf(xv, w.z, acc[j * 4 + 2]);
                acc[j * 4 + 3] = fmaf(xv, w.w, acc[j * 4 + 3]);
            }
        }
        __syncthreads();
    }

    if (row < NN) {
        float d = 1.f;
        if (SCALED) d = g_dinv[row];
#pragma unroll
        for (int j = 0; j < 16; j++) {
            float4 o;
            o.x = acc[j * 4 + 0]; o.y = acc[j * 4 + 1];
            o.z = acc[j * 4 + 2]; o.w = acc[j * 4 + 3];
            if (RELUOUT) {
                o.x = fmaxf(o.x + bias[j * 4 + 0], 0.f);
                o.y = fmaxf(o.y + bias[j * 4 + 1], 0.f);
                o.z = fmaxf(o.z + bias[j * 4 + 2], 0.f);
                o.w = fmaxf(o.w + bias[j * 4 + 3], 0.f);
            } else if (SCALED) {
                o.x *= d; o.y *= d; o.z *= d; o.w *= d;
            }
            *(float4*)&out[(long)row * 64 + j * 4] = o;
        }
    }
}

// ---------------- edge scatter: acc[dst] += g[src], 128-bit vector atomics ----------------
// 16 lanes per edge; each lane: 1x LDG.128 gather + 1x RED.128
__global__ void __launch_bounds__(256) scatter_k(const int* __restrict__ ei) {
    long long idx = (long long)blockIdx.x * blockDim.x + threadIdx.x;
    int e = (int)(idx >> 4);
    int l = (int)(idx & 15);
    if (e >= EE) return;
    int s = ei[e];
    int d = ei[EE + e];
    float4 v = __ldg(reinterpret_cast<const float4*>(g_g) + ((long)s * 16 + l));
    atomicAdd(reinterpret_cast<float4*>(g_acc) + ((long)d * 16 + l), v);
}

// ---------------- finalize conv (+bias) and accumulate next-BN stats ----------------
__global__ void __launch_bounds__(256) finstats_k(const float* __restrict__ bias) {
    int c   = threadIdx.x & 63;
    int rep = threadIdx.x >> 6;   // 0..3
    double s = 0.0, q = 0.0;
    for (int r = blockIdx.x * 4 + rep; r < NN; r += gridDim.x * 4) {
        float d = g_dinv[r];
        int idx = r * 64 + c;
        float v = d * (g_acc[idx] + g_g[idx]) + bias[c];
        g_pre[idx] = v;
        s += (double)v;
        q += (double)v * (double)v;
    }
    __shared__ double ss[256], qq[256];
    ss[threadIdx.x] = s; qq[threadIdx.x] = q;
    __syncthreads();
    if (threadIdx.x < 64) {
        s = ss[c] + ss[c + 64] + ss[c + 128] + ss[c + 192];
        q = qq[c] + qq[c + 64] + qq[c + 128] + qq[c + 192];
        atomicAdd(&g_sum[c], s);
        atomicAdd(&g_sqs[c], q);
    }
}

// ---------------- final BN apply ----------------
__global__ void __launch_bounds__(256) bnapply_k(const float* __restrict__ gam,
                                                 const float* __restrict__ bet,
                                                 float* __restrict__ out) {
    int idx = blockIdx.x * blockDim.x + threadIdx.x;
    if (idx >= NN * HD) return;
    int c = idx & 63;
    double m = g_sum[c] / (double)NN;
    double v = g_sqs[c] / (double)NN - m * m;
    float scl = gam[c] * rsqrtf((float)v + EPSV);
    out[idx] = (g_pre[idx] - (float)m) * scl + bet[c];
}

// ---------------- launch ----------------
extern "C" void kernel_launch(void* const* d_in, const int* in_sizes, int n_in,
                              void* d_out, int out_size) {
    const float* x       = (const float*)d_in[0];
    const int*   ei      = (const int*)d_in[1];     // int32 (JAX default randint dtype)
    const float* bn_in_g = (const float*)d_in[2];
    const float* bn_in_b = (const float*)d_in[3];
    const float* Wp      = (const float*)d_in[4];
    const float* bp      = (const float*)d_in[5];
    const float* W1      = (const float*)d_in[6];
    const float* b1      = (const float*)d_in[7];
    const float* bn1_g   = (const float*)d_in[8];
    const float* bn1_b   = (const float*)d_in[9];
    const float* W2      = (const float*)d_in[10];
    const float* b2      = (const float*)d_in[11];
    const float* bn2_g   = (const float*)d_in[12];
    const float* bn2_b   = (const float*)d_in[13];
    float* out = (float*)d_out;

    const int GB_N    = (NN + 255) / 256;            // 391
    const int GB_E    = (EE + 255) / 256;            // 6250
    const int GB_GEMM = (NN + 127) / 128;            // 782
    const int GB_ACC  = (NN * 16 + 255) / 256;       // 6250
    const int GB_SCAT = (int)(((long long)EE * 16 + 255) / 256);  // 100000
    const int GB_OUT  = (NN * HD + 255) / 256;       // 25000

    // degree + input BN stats
    zero_init_k<<<GB_N, 256>>>();
    deg_k<<<GB_E, 256>>>(ei);
    statsx_k<<<256, 256>>>(x);
    dinv_k<<<GB_N, 256>>>();

    // h0 = relu(BN(x) @ Wp + bp)
    gemm_k<IND, true, false, true, false><<<GB_GEMM, 128>>>(x, -1, Wp, bp, bn_in_g, bn_in_b, 0);

    // conv1: g = dinv * (h0 @ W1); acc = scatter; pre = dinv*(acc+g)+b1 (+bn1 stats)
    gemm_k<HD, false, false, false, true><<<GB_GEMM, 128>>>(nullptr, 0, W1, nullptr, nullptr, nullptr, 1);
    zero_acc_k<<<GB_ACC, 256>>>();
    scatter_k<<<GB_SCAT, 256>>>(ei);
    finstats_k<<<256, 256>>>(b1);

    // conv2: g = dinv * (relu(BN1(pre)) @ W2); scatter; pre = dinv*(acc+g)+b2 (+bn2 stats)
    gemm_k<HD, true, true, false, true><<<GB_GEMM, 128>>>(nullptr, 3, W2, nullptr, bn1_g, bn1_b, 1);
    zero_acc_k<<<GB_ACC, 256>>>();
    scatter_k<<<GB_SCAT, 256>>>(ei);
    finstats_k<<<256, 256>>>(b2);

    // out = BN2(pre)
    bnapply_k<<<GB_OUT, 256>>>(bn2_g, bn2_b, out);
}

// round 7
// speedup vs baseline: 1.5004x; 1.1397x over previous
#include <cuda_runtime.h>
#include <cstdint>

#define NN 100000
#define EE 1600000
#define IND 128
#define HD  64
#define EPSV 1e-5f
#define SCB 391   // ceil(NN/256)

// ---------------- scratch (device globals: allocation-free) ----------------
__device__ __align__(16) float  g_h0 [(size_t)NN * HD];
__device__ __align__(16) float  g_g  [(size_t)NN * HD];
__device__ __align__(16) float  g_pre[(size_t)NN * HD];
__device__ float  g_dinv[NN];
__device__ int    g_deg [NN];
__device__ int    g_rp  [NN + 1];
__device__ int    g_cur [NN];
__device__ int    g_col [EE];
__device__ int    g_bsum[512];
__device__ int    g_boff[512];
__device__ double g_sum [IND];
__device__ double g_sqs [IND];

__device__ __forceinline__ float* bufptr(int s) {
    switch (s) {
        case 0: return g_h0;
        case 1: return g_g;
        default: return g_pre;
    }
}

// ---------------- init ----------------
__global__ void zero_init_k() {   // deg + stats(128)
    int i = blockIdx.x * blockDim.x + threadIdx.x;
    if (i < NN) g_deg[i] = 0;
    if (i < IND) { g_sum[i] = 0.0; g_sqs[i] = 0.0; }
}

__global__ void zstats_k() {      // zero 64-col stats between layers
    int i = threadIdx.x;
    g_sum[i] = 0.0; g_sqs[i] = 0.0;
}

// ---------------- degree ----------------
__global__ void deg_k(const int* __restrict__ ei) {
    int e = blockIdx.x * blockDim.x + threadIdx.x;
    if (e < EE) atomicAdd(&g_deg[ei[EE + e]], 1);
}

__global__ void dinv_k() {
    int i = blockIdx.x * blockDim.x + threadIdx.x;
    if (i < NN) g_dinv[i] = rsqrtf((float)(g_deg[i] + 1));   // +1 = self loop
}

// ---------------- CSR build: 3-step exclusive scan + fill ----------------
__global__ void scan1_k() {
    __shared__ int sh[256];
    int i = blockIdx.x * 256 + threadIdx.x;
    int v = (i < NN) ? g_deg[i] : 0;
    sh[threadIdx.x] = v; __syncthreads();
    for (int d = 1; d < 256; d <<= 1) {
        int t = (threadIdx.x >= d) ? sh[threadIdx.x - d] : 0;
        __syncthreads();
        sh[threadIdx.x] += t;
        __syncthreads();
    }
    if (i < NN) g_rp[i] = sh[threadIdx.x] - v;      // exclusive within block
    if (threadIdx.x == 255) g_bsum[blockIdx.x] = sh[255];
}

__global__ void scan2_k() {
    __shared__ int sh[512];
    int t = threadIdx.x;
    int v = (t < SCB) ? g_bsum[t] : 0;
    sh[t] = v; __syncthreads();
    for (int d = 1; d < 512; d <<= 1) {
        int u = (t >= d) ? sh[t - d] : 0;
        __syncthreads();
        sh[t] += u;
        __syncthreads();
    }
    if (t < SCB) g_boff[t] = sh[t] - v;             // exclusive block offsets
}

__global__ void scan3_k() {
    int i = blockIdx.x * 256 + threadIdx.x;
    if (i < NN) {
        int r = g_rp[i] + g_boff[blockIdx.x];
        g_rp[i] = r;
        g_cur[i] = r;
    }
    if (i == 0) g_rp[NN] = EE;
}

__global__ void fill_k(const int* __restrict__ ei) {
    int e = blockIdx.x * blockDim.x + threadIdx.x;
    if (e < EE) {
        int s = ei[e];
        int d = ei[EE + e];
        int pos = atomicAdd(&g_cur[d], 1);
        g_col[pos] = s;
    }
}

// ---------------- BN stats over x [N,128] ----------------
__global__ void __launch_bounds__(256) statsx_k(const float* __restrict__ X) {
    int c   = threadIdx.x & 127;
    int rep = threadIdx.x >> 7;
    double s = 0.0, q = 0.0;
    for (int r = blockIdx.x * 2 + rep; r < NN; r += gridDim.x * 2) {
        float v = X[(long)r * IND + c];
        s += (double)v;
        q += (double)v * (double)v;
    }
    __shared__ double ss[256], qq[256];
    ss[threadIdx.x] = s; qq[threadIdx.x] = q;
    __syncthreads();
    if (threadIdx.x < 128) {
        s = ss[c] + ss[c + 128];
        q = qq[c] + qq[c + 128];
        atomicAdd(&g_sum[c], s);
        atomicAdd(&g_sqs[c], q);
    }
}

// ---------------- fused GEMM: [N,IN] @ [IN,64] ----------------
template<int IN, bool BNIN, bool RELUIN, bool RELUOUT, bool SCALED>
__global__ void __launch_bounds__(128) gemm_k(
    const float* __restrict__ Xext, int xsel,
    const float* __restrict__ W,
    const float* __restrict__ bias,
    const float* __restrict__ bng,
    const float* __restrict__ bnb,
    int osel)
{
    __shared__ float Ws[32 * 64];
    __shared__ float xs[128 * 33];
    __shared__ float sc[IND], sh[IND];

    const float* X  = (xsel < 0) ? Xext : bufptr(xsel);
    float*      out = bufptr(osel);

    int tid = threadIdx.x;
    if (BNIN) {
        if (tid < IN) {
            double m = g_sum[tid] / (double)NN;
            double v = g_sqs[tid] / (double)NN - m * m;
            float  s = bng[tid] * rsqrtf((float)v + EPSV);
            sc[tid] = s;
            sh[tid] = bnb[tid] - (float)m * s;
        }
        __syncthreads();
    }

    int row = blockIdx.x * 128 + tid;
    float acc[64];
#pragma unroll
    for (int j = 0; j < 64; j++) acc[j] = 0.f;

    for (int k0 = 0; k0 < IN; k0 += 32) {
#pragma unroll
        for (int i = 0; i < 16; i++) {
            int idx = i * 128 + tid;
            Ws[idx] = W[(k0 + (idx >> 6)) * 64 + (idx & 63)];
        }
        int kk = tid & 31, rbase = tid >> 5;
#pragma unroll
        for (int i = 0; i < 32; i++) {
            int r  = i * 4 + rbase;
            int gr = blockIdx.x * 128 + r;
            float v = (gr < NN) ? X[(long)gr * IN + k0 + kk] : 0.f;
            if (BNIN) {
                v = v * sc[k0 + kk] + sh[k0 + kk];
                if (RELUIN) v = fmaxf(v, 0.f);
            }
            xs[r * 33 + kk] = v;
        }
        __syncthreads();
#pragma unroll
        for (int q = 0; q < 32; q++) {
            float xv = xs[tid * 33 + q];
#pragma unroll
            for (int j = 0; j < 16; j++) {
                float4 w = *(const float4*)&Ws[q * 64 + j * 4];
                acc[j * 4 + 0] = fmaf(xv, w.x, acc[j * 4 + 0]);
                acc[j * 4 + 1] = fmaf(xv, w.y, acc[j * 4 + 1]);
                acc[j * 4 + 2] = fmaf(xv, w.z, acc[j * 4 + 2]);
                acc[j * 4 + 3] = fmaf(xv, w.w, acc[j * 4 + 3]);
            }
        }
        __syncthreads();
    }

    if (row < NN) {
        float d = 1.f;
        if (SCALED) d = g_dinv[row];
#pragma unroll
        for (int j = 0; j < 16; j++) {
            float4 o;
            o.x = acc[j * 4 + 0]; o.y = acc[j * 4 + 1];
            o.z = acc[j * 4 + 2]; o.w = acc[j * 4 + 3];
            if (RELUOUT) {
                o.x = fmaxf(o.x + bias[j * 4 + 0], 0.f);
                o.y = fmaxf(o.y + bias[j * 4 + 1], 0.f);
                o.z = fmaxf(o.z + bias[j * 4 + 2], 0.f);
                o.w = fmaxf(o.w + bias[j * 4 + 3], 0.f);
            } else if (SCALED) {
                o.x *= d; o.y *= d; o.z *= d; o.w *= d;
            }
            *(float4*)&out[(long)row * 64 + j * 4] = o;
        }
    }
}

// ---------------- atomic-free gather aggregation ----------------
// pre[d] = dinv[d]*( g[d] + sum_{s in CSR row d} g[s] ) + bias
// 16 lanes per node; lane l owns float4 columns [4l,4l+4)
__global__ void __launch_bounds__(256) gather_k(const float* __restrict__ bias) {
    int tid  = threadIdx.x;
    int node = blockIdx.x * 16 + (tid >> 4);     // NN = 6250*16 exactly
    int l    = tid & 15;
    unsigned gmask = 0xFFFFu << (threadIdx.x & 16);   // this 16-lane group

    const float4* G = reinterpret_cast<const float4*>(g_g);
    float4 a = __ldg(G + ((long)node * 16 + l));      // self loop
    int p0 = g_rp[node], p1 = g_rp[node + 1];

    for (int p = p0; p < p1; p += 16) {
        int n = p1 - p; if (n > 16) n = 16;
        int cs = (l < n) ? g_col[p + l] : 0;
        for (int j = 0; j < n; j++) {
            int s = __shfl_sync(gmask, cs, j, 16);
            float4 v = __ldg(G + ((long)s * 16 + l));
            a.x += v.x; a.y += v.y; a.z += v.z; a.w += v.w;
        }
    }

    float dv = g_dinv[node];
    float4 b4 = *(const float4*)(bias + l * 4);
    float4 o;
    o.x = dv * a.x + b4.x;
    o.y = dv * a.y + b4.y;
    o.z = dv * a.z + b4.z;
    o.w = dv * a.w + b4.w;
    *(float4*)&g_pre[(long)node * 64 + l * 4] = o;
}

// ---------------- stats over g_pre [N,64] ----------------
__global__ void __launch_bounds__(256) statsh_k() {
    int c   = threadIdx.x & 63;
    int rep = threadIdx.x >> 6;
    double s = 0.0, q = 0.0;
    for (int r = blockIdx.x * 4 + rep; r < NN; r += gridDim.x * 4) {
        float v = g_pre[r * 64 + c];
        s += (double)v;
        q += (double)v * (double)v;
    }
    __shared__ double ss[256], qq[256];
    ss[threadIdx.x] = s; qq[threadIdx.x] = q;
    __syncthreads();
    if (threadIdx.x < 64) {
        s = ss[c] + ss[c + 64] + ss[c + 128] + ss[c + 192];
        q = qq[c] + qq[c + 64] + qq[c + 128] + qq[c + 192];
        atomicAdd(&g_sum[c], s);
        atomicAdd(&g_sqs[c], q);
    }
}

// ---------------- final BN apply ----------------
__global__ void __launch_bounds__(256) bnapply_k(const float* __restrict__ gam,
                                                 const float* __restrict__ bet,
                                                 float* __restrict__ out) {
    int idx = blockIdx.x * blockDim.x + threadIdx.x;
    if (idx >= NN * HD) return;
    int c = idx & 63;
    double m = g_sum[c] / (double)NN;
    double v = g_sqs[c] / (double)NN - m * m;
    float scl = gam[c] * rsqrtf((float)v + EPSV);
    out[idx] = (g_pre[idx] - (float)m) * scl + bet[c];
}

// ---------------- launch ----------------
extern "C" void kernel_launch(void* const* d_in, const int* in_sizes, int n_in,
                              void* d_out, int out_size) {
    const float* x       = (const float*)d_in[0];
    const int*   ei      = (const int*)d_in[1];
    const float* bn_in_g = (const float*)d_in[2];
    const float* bn_in_b = (const float*)d_in[3];
    const float* Wp      = (const float*)d_in[4];
    const float* bp      = (const float*)d_in[5];
    const float* W1      = (const float*)d_in[6];
    const float* b1      = (const float*)d_in[7];
    const float* bn1_g   = (const float*)d_in[8];
    const float* bn1_b   = (const float*)d_in[9];
    const float* W2      = (const float*)d_in[10];
    const float* b2      = (const float*)d_in[11];
    const float* bn2_g   = (const float*)d_in[12];
    const float* bn2_b   = (const float*)d_in[13];
    float* out = (float*)d_out;

    const int GB_N    = (NN + 255) / 256;            // 391
    const int GB_E    = (EE + 255) / 256;            // 6250
    const int GB_GEMM = (NN + 127) / 128;            // 782
    const int GB_GATH = NN / 16;                     // 6250
    const int GB_OUT  = (NN * HD + 255) / 256;       // 25000

    // degree + input BN stats + CSR
    zero_init_k<<<GB_N, 256>>>();
    deg_k<<<GB_E, 256>>>(ei);
    statsx_k<<<256, 256>>>(x);
    dinv_k<<<GB_N, 256>>>();
    scan1_k<<<SCB, 256>>>();
    scan2_k<<<1, 512>>>();
    scan3_k<<<SCB, 256>>>();
    fill_k<<<GB_E, 256>>>(ei);

    // h0 = relu(BN(x) @ Wp + bp)
    gemm_k<IND, true, false, true, false><<<GB_GEMM, 128>>>(x, -1, Wp, bp, bn_in_g, bn_in_b, 0);

    // conv1: g = dinv*(h0 @ W1); pre = dinv*(gather+self)+b1; bn1 stats
    gemm_k<HD, false, false, false, true><<<GB_GEMM, 128>>>(nullptr, 0, W1, nullptr, nullptr, nullptr, 1);
    zstats_k<<<1, 64>>>();
    gather_k<<<GB_GATH, 256>>>(b1);
    statsh_k<<<256, 256>>>();

    // conv2: g = dinv*(relu(BN1(pre)) @ W2); pre = dinv*(gather+self)+b2; bn2 stats
    gemm_k<HD, true, true, false, true><<<GB_GEMM, 128>>>(nullptr, 2, W2, nullptr, bn1_g, bn1_b, 1);
    zstats_k<<<1, 64>>>();
    gather_k<<<GB_GATH, 256>>>(b2);
    statsh_k<<<256, 256>>>();

    // out = BN2(pre)
    bnapply_k<<<GB_OUT, 256>>>(bn2_g, bn2_b, out);
}